// round 8
// baseline (speedup 1.0000x reference)
#include <cuda_runtime.h>
#include <cuda_bf16.h>

// Idx2PixelLayer — R6: two temporal passes over the same coords, each pass
// only processes points whose row index i0 falls in half of the table.
// Each 67MB half fits in the 126MB L2, so repeat-touched pixels (≈38% of
// touches) hit L2 instead of DRAM. Table loads use L2::evict_last to pin the
// resident half; coords (__ldcs) and out (__stcs) stream around it.

static constexpr int   HW   = 2048;
static constexpr int   CH   = 8;
static constexpr float MODV = 2044.0f;   // H - 4

struct F8 { float v[8]; };

__device__ __forceinline__ F8 ldg_keep32(const float* p) {
    F8 r;
    asm volatile("ld.global.nc.L2::evict_last.v8.b32 {%0,%1,%2,%3,%4,%5,%6,%7}, [%8];"
                 : "=f"(r.v[0]), "=f"(r.v[1]), "=f"(r.v[2]), "=f"(r.v[3]),
                   "=f"(r.v[4]), "=f"(r.v[5]), "=f"(r.v[6]), "=f"(r.v[7])
                 : "l"(p));
    return r;
}

__global__ __launch_bounds__(256)
void idx2pixel_pass(const float* __restrict__ coords,
                    const float* __restrict__ visible,
                    float* __restrict__ out,
                    int n, int rowLo, int rowHi)
{
    int t = blockIdx.x * blockDim.x + threadIdx.x;
    if (t >= n) return;

    float2 co = __ldcs(reinterpret_cast<const float2*>(coords) + t);

    // floor-mod (python semantics) then +1 ; c in [1, 2045) < 2048, so the
    // reference's zero-mask (c0 > 2048) can never fire.
    float c0 = fmodf(co.x - 1.0f, MODV); if (c0 < 0.0f) c0 += MODV; c0 += 1.0f;
    float c1 = fmodf(co.y - 1.0f, MODV); if (c1 < 0.0f) c1 += MODV; c1 += 1.0f;

    float f0 = floorf(c0), f1 = floorf(c1);
    int i0 = (int)f0;
    if (i0 < rowLo || i0 >= rowHi) return;     // other pass handles it

    float d0 = c0 - f0, d1 = c1 - f1;
    int i1 = (int)f1;

    // Row i0:   [top_left | bottom_left]  (cols i1, i1+1) = 64B contiguous
    // Row i0+1: [top_right | bottom_right]
    const float* rowA = visible + ((size_t)i0 * HW + i1) * CH;
    const float* rowB = rowA + (size_t)HW * CH;

    F8 tl = ldg_keep32(rowA);
    F8 bl = ldg_keep32(rowA + 8);
    F8 tr = ldg_keep32(rowB);
    F8 br = ldg_keep32(rowB + 8);

    float o[8];
    #pragma unroll
    for (int k = 0; k < 8; k++) {
        float mt = tr.v[k] + d0 * (tl.v[k] - tr.v[k]);
        float mb = br.v[k] + d0 * (bl.v[k] - br.v[k]);
        o[k] = mb + d1 * (mt - mb);
    }

    float4* dst = reinterpret_cast<float4*>(out + (size_t)t * CH);
    __stcs(dst + 0, make_float4(o[0], o[1], o[2], o[3]));
    __stcs(dst + 1, make_float4(o[4], o[5], o[6], o[7]));
}

extern "C" void kernel_launch(void* const* d_in, const int* in_sizes, int n_in,
                              void* d_out, int out_size)
{
    const float* coords  = (const float*)d_in[0];   // (N, 2) float32
    const float* visible = (const float*)d_in[1];   // (2048, 2048, 8) float32
    float* out = (float*)d_out;                     // (N, 8) float32

    int n = in_sizes[0] / 2;
    int threads = 256;
    int blocks = (n + threads - 1) / threads;

    // Pass 1: rows [0, 1024)  -> touches table rows [0, 1025): ~67MB, fits L2.
    idx2pixel_pass<<<blocks, threads>>>(coords, visible, out, n, 0, 1024);
    // Pass 2: rows [1024, 2046)
    idx2pixel_pass<<<blocks, threads>>>(coords, visible, out, n, 1024, 2046);
}

// round 12
// speedup vs baseline: 1.0386x; 1.0386x over previous
#include <cuda_runtime.h>
#include <cuda_bf16.h>

// Idx2PixelLayer — R8: two temporal passes (row halves, each 67MB half fits
// L2 -> repeat pixel touches hit L2), now with TWO points per thread per pass
// so per-warp in-flight gathers match the single-pass kernel (expected 1 of 2
// points in-range per thread). Combines R6's traffic reduction (~199->~148MB)
// with R0's DRAM efficiency.

static constexpr int   HW   = 2048;
static constexpr int   CH   = 8;
static constexpr float MODV = 2044.0f;   // H - 4

struct F8 { float v[8]; };

__device__ __forceinline__ F8 ldg_keep32(const float* p) {
    F8 r;
    asm volatile("ld.global.nc.L2::evict_last.v8.b32 {%0,%1,%2,%3,%4,%5,%6,%7}, [%8];"
                 : "=f"(r.v[0]), "=f"(r.v[1]), "=f"(r.v[2]), "=f"(r.v[3]),
                   "=f"(r.v[4]), "=f"(r.v[5]), "=f"(r.v[6]), "=f"(r.v[7])
                 : "l"(p));
    return r;
}

__device__ __forceinline__ void prep(float cx, float cy, const float* visible,
                                     const float*& rowA, const float*& rowB,
                                     float& d0, float& d1, int& i0)
{
    // floor-mod (python semantics) then +1 ; c in [1,2045) < 2048, so the
    // reference's zero-mask (c0 > 2048) can never fire.
    float c0 = fmodf(cx - 1.0f, MODV); if (c0 < 0.0f) c0 += MODV; c0 += 1.0f;
    float c1 = fmodf(cy - 1.0f, MODV); if (c1 < 0.0f) c1 += MODV; c1 += 1.0f;
    float f0 = floorf(c0), f1 = floorf(c1);
    d0 = c0 - f0; d1 = c1 - f1;
    i0 = (int)f0;
    int i1 = (int)f1;
    rowA = visible + ((size_t)i0 * HW + i1) * CH;   // [tl | bl] 64B
    rowB = rowA + (size_t)HW * CH;                  // [tr | br] 64B
}

__device__ __forceinline__ void bilerp_store(const F8& tl, const F8& bl,
                                             const F8& tr, const F8& br,
                                             float d0, float d1,
                                             float* outp)
{
    float o[8];
    #pragma unroll
    for (int k = 0; k < 8; k++) {
        float mt = tr.v[k] + d0 * (tl.v[k] - tr.v[k]);
        float mb = br.v[k] + d0 * (bl.v[k] - br.v[k]);
        o[k] = mb + d1 * (mt - mb);
    }
    float4* dst = reinterpret_cast<float4*>(outp);
    __stcs(dst + 0, make_float4(o[0], o[1], o[2], o[3]));
    __stcs(dst + 1, make_float4(o[4], o[5], o[6], o[7]));
}

__global__ __launch_bounds__(256)
void idx2pixel_pass2(const float* __restrict__ coords,
                     const float* __restrict__ visible,
                     float* __restrict__ out,
                     int pairs, int rowLo, int rowHi)
{
    int t = blockIdx.x * blockDim.x + threadIdx.x;
    if (t >= pairs) return;

    float4 co = __ldcs(reinterpret_cast<const float4*>(coords) + t);

    const float *aA, *bA, *aB, *bB;
    float d0A, d1A, d0B, d1B;
    int i0A, i0B;
    prep(co.x, co.y, visible, aA, bA, d0A, d1A, i0A);
    prep(co.z, co.w, visible, aB, bB, d0B, d1B, i0B);

    bool actA = (i0A >= rowLo) & (i0A < rowHi);
    bool actB = (i0B >= rowLo) & (i0B < rowHi);

    F8 tlA, blA, trA, brA, tlB, blB, trB, brB;
    // Issue all in-range gathers before any compute (max MLP).
    if (actA) { tlA = ldg_keep32(aA); blA = ldg_keep32(aA + 8); }
    if (actB) { tlB = ldg_keep32(aB); blB = ldg_keep32(aB + 8); }
    if (actA) { trA = ldg_keep32(bA); brA = ldg_keep32(bA + 8); }
    if (actB) { trB = ldg_keep32(bB); brB = ldg_keep32(bB + 8); }

    float* outBase = out + (size_t)t * 2 * CH;
    if (actA) bilerp_store(tlA, blA, trA, brA, d0A, d1A, outBase);
    if (actB) bilerp_store(tlB, blB, trB, brB, d0B, d1B, outBase + CH);
}

// Tail for odd N (N=1e6 is even; keep correct anyway).
__global__ void idx2pixel_tail(const float* __restrict__ coords,
                               const float* __restrict__ visible,
                               float* __restrict__ out, int idx)
{
    float2 co = reinterpret_cast<const float2*>(coords)[idx];
    const float *ra, *rb; float d0, d1; int i0;
    prep(co.x, co.y, visible, ra, rb, d0, d1, i0);
    F8 tl = ldg_keep32(ra), bl = ldg_keep32(ra + 8);
    F8 tr = ldg_keep32(rb), br = ldg_keep32(rb + 8);
    float o[8];
    #pragma unroll
    for (int k = 0; k < 8; k++) {
        float mt = tr.v[k] + d0 * (tl.v[k] - tr.v[k]);
        float mb = br.v[k] + d0 * (bl.v[k] - br.v[k]);
        o[k] = mb + d1 * (mt - mb);
    }
    float4* dst = reinterpret_cast<float4*>(out + (size_t)idx * CH);
    dst[0] = make_float4(o[0], o[1], o[2], o[3]);
    dst[1] = make_float4(o[4], o[5], o[6], o[7]);
}

extern "C" void kernel_launch(void* const* d_in, const int* in_sizes, int n_in,
                              void* d_out, int out_size)
{
    const float* coords  = (const float*)d_in[0];   // (N, 2) float32
    const float* visible = (const float*)d_in[1];   // (2048, 2048, 8) float32
    float* out = (float*)d_out;                     // (N, 8) float32

    int n = in_sizes[0] / 2;   // points
    int pairs = n / 2;
    int threads = 256;
    int blocks = (pairs + threads - 1) / threads;

    if (pairs > 0) {
        idx2pixel_pass2<<<blocks, threads>>>(coords, visible, out, pairs, 0, 1024);
        idx2pixel_pass2<<<blocks, threads>>>(coords, visible, out, pairs, 1024, 2046);
    }
    if (n & 1) idx2pixel_tail<<<1, 1>>>(coords, visible, out, n - 1);
}